// round 1
// baseline (speedup 1.0000x reference)
#include <cuda_runtime.h>
#include <cuda_bf16.h>

// out[i] = -0.5*(df + D) * log(1 + sum_j (X[i,j]-mean[j])^2 / df)
// X: [N, D] fp32, mean: [D] fp32, df: [1] fp32, out: [N] fp32
// N=8192, D=4096 in the dataset, but we derive from in_sizes.

__global__ __launch_bounds__(256, 8)
void row_logden_kernel(const float4* __restrict__ X,
                       const float4* __restrict__ mean,
                       const float* __restrict__ df,
                       float* __restrict__ out,
                       int ncols4, int d_full)
{
    const int row = blockIdx.x;
    const float4* xr = X + (size_t)row * ncols4;

    float acc = 0.0f;

    // ncols4 = 1024, blockDim = 256 -> exactly 4 iterations.
    // Unroll manually for front-batched independent loads (MLP).
    int i = threadIdx.x;
    #pragma unroll 4
    for (; i + 3 * 256 < ncols4; i += 4 * 256) {
        float4 x0 = X == nullptr ? make_float4(0,0,0,0) : xr[i];
        float4 x1 = xr[i + 256];
        float4 x2 = xr[i + 512];
        float4 x3 = xr[i + 768];
        float4 m0 = mean[i];
        float4 m1 = mean[i + 256];
        float4 m2 = mean[i + 512];
        float4 m3 = mean[i + 768];

        float a;
        a = x0.x - m0.x; acc = fmaf(a, a, acc);
        a = x0.y - m0.y; acc = fmaf(a, a, acc);
        a = x0.z - m0.z; acc = fmaf(a, a, acc);
        a = x0.w - m0.w; acc = fmaf(a, a, acc);
        a = x1.x - m1.x; acc = fmaf(a, a, acc);
        a = x1.y - m1.y; acc = fmaf(a, a, acc);
        a = x1.z - m1.z; acc = fmaf(a, a, acc);
        a = x1.w - m1.w; acc = fmaf(a, a, acc);
        a = x2.x - m2.x; acc = fmaf(a, a, acc);
        a = x2.y - m2.y; acc = fmaf(a, a, acc);
        a = x2.z - m2.z; acc = fmaf(a, a, acc);
        a = x2.w - m2.w; acc = fmaf(a, a, acc);
        a = x3.x - m3.x; acc = fmaf(a, a, acc);
        a = x3.y - m3.y; acc = fmaf(a, a, acc);
        a = x3.z - m3.z; acc = fmaf(a, a, acc);
        a = x3.w - m3.w; acc = fmaf(a, a, acc);
    }
    // Tail (handles D not divisible by 4096-wide chunks)
    for (; i < ncols4; i += 256) {
        float4 x = xr[i];
        float4 m = mean[i];
        float a;
        a = x.x - m.x; acc = fmaf(a, a, acc);
        a = x.y - m.y; acc = fmaf(a, a, acc);
        a = x.z - m.z; acc = fmaf(a, a, acc);
        a = x.w - m.w; acc = fmaf(a, a, acc);
    }

    // Warp reduce
    #pragma unroll
    for (int off = 16; off > 0; off >>= 1)
        acc += __shfl_xor_sync(0xFFFFFFFFu, acc, off);

    __shared__ float warp_sums[8];
    const int lane = threadIdx.x & 31;
    const int wid = threadIdx.x >> 5;
    if (lane == 0) warp_sums[wid] = acc;
    __syncthreads();

    if (wid == 0) {
        float s = (lane < (blockDim.x >> 5)) ? warp_sums[lane] : 0.0f;
        #pragma unroll
        for (int off = 4; off > 0; off >>= 1)
            s += __shfl_xor_sync(0xFFFFFFFFu, s, off);
        if (lane == 0) {
            const float dfv = df[0];
            // log(1 + s/df) via log1pf for accuracy
            const float logden = log1pf(s / dfv);
            out[row] = -0.5f * (dfv + (float)d_full) * logden;
        }
    }
}

extern "C" void kernel_launch(void* const* d_in, const int* in_sizes, int n_in,
                              void* d_out, int out_size)
{
    const float* X    = (const float*)d_in[0];
    const float* mean = (const float*)d_in[1];
    const float* df   = (const float*)d_in[2];
    float* out        = (float*)d_out;

    const int D = in_sizes[1];          // 4096
    const int N = in_sizes[0] / D;      // 8192
    const int ncols4 = D / 4;           // 1024 (D is a multiple of 4 here)

    row_logden_kernel<<<N, 256>>>((const float4*)X, (const float4*)mean, df,
                                  out, ncols4, D);
}